// round 10
// baseline (speedup 1.0000x reference)
#include <cuda_runtime.h>
#include <cstdint>

#define NH 32     // hidden
#define RK 6      // rank
#define BB 256    // batch
#define TT 2048   // time
#define DI 64     // input dim
#define DO 32     // output dim

#define RING  128
#define RINGM 127

// 64 MB scratch for pre-scaled x-projection (device global: allocation-free)
__device__ float g_xp[(size_t)BB * TT * NH];

#define L2E2 2.885390081777926815f   // 2*log2(e)

// Packed fp32x2 ops (Blackwell)
__device__ __forceinline__ float2 fma2(const float2 a, const float2 b, const float2 c) {
    float2 d;
    asm("fma.rn.f32x2 %0, %1, %2, %3;"
        : "=l"(*(unsigned long long*)&d)
        : "l"(*(const unsigned long long*)&a),
          "l"(*(const unsigned long long*)&b),
          "l"(*(const unsigned long long*)&c));
    return d;
}
__device__ __forceinline__ float2 add2(const float2 a, const float2 b) {
    float2 d;
    asm("add.rn.f32x2 %0, %1, %2;"
        : "=l"(*(unsigned long long*)&d)
        : "l"(*(const unsigned long long*)&a),
          "l"(*(const unsigned long long*)&b));
    return d;
}

// ---------------------------------------------------------------------------
// Kernel 1: g_xp[b,t,n] = L2E2 * (sum_i inputs[b,t,i]*W_in[n,i] + bias[n])
// (proven 90us version, unchanged)
// ---------------------------------------------------------------------------
__global__ void __launch_bounds__(256) xproj_kernel(
    const float* __restrict__ inp, const float* __restrict__ Win,
    const float* __restrict__ bias)
{
    __shared__ float u[64 * DI];
    __shared__ float Wsm[NH][DI + 1];

    const int tid = threadIdx.x;

    for (int idx = tid; idx < NH * DI; idx += 256)
        Wsm[idx / DI][idx % DI] = Win[idx];

    const size_t base = (size_t)blockIdx.x * 64 * DI;
    const float4* gs = (const float4*)(inp + base);
    float4* sd = (float4*)u;
    #pragma unroll
    for (int k2 = 0; k2 < 4; k2++) sd[tid + 256 * k2] = gs[tid + 256 * k2];
    __syncthreads();

    const int n_ = tid & 31;
    const int rg = tid >> 5;

    float2 w2[DI / 2];
    #pragma unroll
    for (int i = 0; i < DI; i += 2)
        w2[i / 2] = make_float2(Wsm[n_][i], Wsm[n_][i + 1]);

    float2 acc[8];
    #pragma unroll
    for (int r = 0; r < 8; r++) acc[r] = make_float2(0.f, 0.f);

    #pragma unroll
    for (int i4 = 0; i4 < DI / 4; i4++) {
        const float2 wlo = w2[2 * i4 + 0];
        const float2 whi = w2[2 * i4 + 1];
        #pragma unroll
        for (int r = 0; r < 8; r++) {
            const float4 u4 = *(const float4*)&u[(rg * 8 + r) * DI + i4 * 4];
            acc[r] = fma2(wlo, make_float2(u4.x, u4.y), acc[r]);
            acc[r] = fma2(whi, make_float2(u4.z, u4.w), acc[r]);
        }
    }

    const float bn = bias[n_];
    const size_t rowbase = (size_t)blockIdx.x * 64;
    #pragma unroll
    for (int r = 0; r < 8; r++)
        g_xp[(rowbase + rg * 8 + r) * NH + n_] = L2E2 * (acc[r].x + acc[r].y + bn);
}

// ---------------------------------------------------------------------------
// Kernel 2: warp-specialized recurrence, TWO batch chains per block.
//   Warp 0 (A):  both p-recurrences interleaved (shared weight regs),
//                writes r to ring[0]/ring[1].
//   Warp 1 (B0): trailing q/h/y for batch0 from ring[0].
//   Warp 2 (B1): trailing q/h/y for batch1 from ring[1].
// tanh = 1 - 2r, r = 1/(exp2(pre')+1), pre' in 2log2e-scaled space.
// Per-chain math identical to the proven 316us kernel (incl. per-step
// __syncwarp in A, which ptxas needs to pipeline the LDS batch).
// ---------------------------------------------------------------------------
__global__ void __launch_bounds__(96) rnn_kernel(
    const float* __restrict__ m, const float* __restrict__ nv,
    const float* __restrict__ Mm, const float* __restrict__ Nm,
    const float* __restrict__ Wout, const float* __restrict__ bout,
    float* __restrict__ out, float* __restrict__ hfin)
{
    __shared__ __align__(16) float ring[2][RING][NH];   // 32 KB
    __shared__ unsigned progress;    // steps produced by A (both chains)
    __shared__ unsigned bdone[2];    // steps consumed by B0/B1

    const int wid = threadIdx.x >> 5;
    const int l   = threadIdx.x & 31;
    const int b0  = blockIdx.x * 2;

    if (threadIdx.x == 0) { progress = 0u; bdone[0] = 0u; bdone[1] = 0u; }
    __syncthreads();

    if (wid == 0) {
        // ================= WARP A: two interleaved chains =================
        float Ml[RK];
        const float ml = m[l];
        #pragma unroll
        for (int j = 0; j < RK; j++) Ml[j] = Mm[l * RK + j];

        float2 wr2[NH / 2];
        float wrsum = 0.f;
        #pragma unroll
        for (int k = 0; k < NH; k += 2) {
            float s0 = ml * nv[k], s1 = ml * nv[k + 1];
            #pragma unroll
            for (int j = 0; j < RK; j++) {
                s0 = fmaf(Ml[j], Nm[k * RK + j], s0);
                s1 = fmaf(Ml[j], Nm[(k + 1) * RK + j], s1);
            }
            wrsum += s0 + s1;
            wr2[k / 2] = make_float2(-0.2f * L2E2 * s0, -0.2f * L2E2 * s1);
        }
        wrsum *= 0.1f * L2E2;

        const float* xp0 = g_xp + (size_t)b0 * TT * NH + l;
        const float* xp1 = xp0 + (size_t)TT * NH;
        float p0 = 0.f, p1 = 0.f;

        float xa0[8], xa1[8], xn0[8], xn1[8];
        #pragma unroll
        for (int i = 0; i < 8; i++) {
            xa0[i] = xp0[(size_t)i * NH];
            xa1[i] = xp1[(size_t)i * NH];
        }

        for (int c = 0; c < TT / 8; c++) {
            const int t0 = c * 8;
            if (c + 1 < TT / 8) {
                #pragma unroll
                for (int i = 0; i < 8; i++) {
                    xn0[i] = xp0[(size_t)(t0 + 8 + i) * NH];
                    xn1[i] = xp1[(size_t)(t0 + 8 + i) * NH];
                }
            }
            #pragma unroll
            for (int s = 0; s < 8; s++) {
                const int t = t0 + s;
                const float pre0 = p0 + xa0[s];
                const float pre1 = p1 + xa1[s];
                float e0, e1;
                asm("ex2.approx.f32 %0, %1;" : "=f"(e0) : "f"(pre0));
                asm("ex2.approx.f32 %0, %1;" : "=f"(e1) : "f"(pre1));
                float r0, r1;
                asm("rcp.approx.f32 %0, %1;" : "=f"(r0) : "f"(e0 + 1.0f));
                asm("rcp.approx.f32 %0, %1;" : "=f"(r1) : "f"(e1 + 1.0f));

                const float pbase0 = fmaf(0.9f, p0, wrsum);   // MUFU shadow
                const float pbase1 = fmaf(0.9f, p1, wrsum);

                ring[0][t & RINGM][l] = r0;
                ring[1][t & RINGM][l] = r1;
                __syncwarp();

                const float4* q0p = (const float4*)ring[0][t & RINGM];
                const float4* q1p = (const float4*)ring[1][t & RINGM];
                float2 a00 = make_float2(0.f, 0.f), a01 = a00, a02 = a00, a03 = a00;
                float2 a10 = a00, a11 = a00, a12 = a00, a13 = a00;
                #pragma unroll
                for (int j = 0; j < NH / 4; j++) {
                    const float4 v0 = q0p[j];
                    const float4 v1 = q1p[j];
                    const float2 lo0 = make_float2(v0.x, v0.y);
                    const float2 hi0 = make_float2(v0.z, v0.w);
                    const float2 lo1 = make_float2(v1.x, v1.y);
                    const float2 hi1 = make_float2(v1.z, v1.w);
                    float2 acc0 = (j & 3) == 0 ? a00 : (j & 3) == 1 ? a01 : (j & 3) == 2 ? a02 : a03;
                    float2 acc1 = (j & 3) == 0 ? a10 : (j & 3) == 1 ? a11 : (j & 3) == 2 ? a12 : a13;
                    acc0 = fma2(wr2[2 * j + 0], lo0, acc0);
                    acc0 = fma2(wr2[2 * j + 1], hi0, acc0);
                    acc1 = fma2(wr2[2 * j + 0], lo1, acc1);
                    acc1 = fma2(wr2[2 * j + 1], hi1, acc1);
                    if ((j & 3) == 0) { a00 = acc0; a10 = acc1; }
                    else if ((j & 3) == 1) { a01 = acc0; a11 = acc1; }
                    else if ((j & 3) == 2) { a02 = acc0; a12 = acc1; }
                    else { a03 = acc0; a13 = acc1; }
                }
                const float2 s0v = add2(add2(a00, a01), add2(a02, a03));
                const float2 s1v = add2(add2(a10, a11), add2(a12, a13));
                p0 = pbase0 + (s0v.x + s0v.y);
                p1 = pbase1 + (s1v.x + s1v.y);
            }
            #pragma unroll
            for (int i = 0; i < 8; i++) { xa0[i] = xn0[i]; xa1[i] = xn1[i]; }

            if ((c & 3) == 3) {
                __threadfence_block();
                __syncwarp();
                if (l == 0) {
                    *(volatile unsigned*)&progress = (unsigned)(t0 + 8);
                    unsigned d0, d1;
                    do {
                        d0 = *(volatile unsigned*)&bdone[0];
                        d1 = *(volatile unsigned*)&bdone[1];
                        const unsigned dm = d0 < d1 ? d0 : d1;
                        if ((int)(t0 + 8) - (int)dm <= RING - 64) break;
                        __nanosleep(100);
                    } while (true);
                }
                __syncwarp();
            }
        }
    } else {
        // ================= WARP B0/B1: trailing q/h/y =================
        const int rs = wid - 1;          // ring select / batch select
        const int b  = b0 + rs;

        float2 wo2[NH / 2];
        float wosum = 0.f;
        #pragma unroll
        for (int k = 0; k < NH; k += 2) {
            const float o0 = Wout[l * NH + k], o1 = Wout[l * NH + k + 1];
            wosum += o0 + o1;
            wo2[k / 2] = make_float2(-0.2f * o0, -0.2f * o1);
        }
        wosum *= 0.1f;
        const float bo = bout[l];

        float* yo = out + (size_t)b * TT * DO + l;
        float q = 0.f, h = 0.f;

        for (int blk = 0; blk < TT / 32; blk++) {
            const int tend = (blk + 1) * 32;
            if (l == 0) {
                while ((int)(*(volatile unsigned*)&progress) < tend)
                    __nanosleep(150);
            }
            __syncwarp();
            __threadfence_block();   // acquire: ring writes visible

            for (int t = blk * 32; t < tend; t++) {
                const float4* r4p = (const float4*)ring[rs][t & RINGM];
                float2 aq0 = make_float2(0.f, 0.f), aq1 = aq0, aq2 = aq0, aq3 = aq0;
                #pragma unroll
                for (int j = 0; j < NH / 4; j++) {
                    const float4 r4 = r4p[j];
                    const float2 lo = make_float2(r4.x, r4.y);
                    const float2 hi = make_float2(r4.z, r4.w);
                    float2 acc = (j & 3) == 0 ? aq0 : (j & 3) == 1 ? aq1 : (j & 3) == 2 ? aq2 : aq3;
                    acc = fma2(wo2[2 * j + 0], lo, acc);
                    acc = fma2(wo2[2 * j + 1], hi, acc);
                    if ((j & 3) == 0) aq0 = acc; else if ((j & 3) == 1) aq1 = acc;
                    else if ((j & 3) == 2) aq2 = acc; else aq3 = acc;
                }
                const float2 sq2 = add2(add2(aq0, aq1), add2(aq2, aq3));
                const float rl = ring[rs][t & RINGM][l];

                q = fmaf(0.9f, q, wosum) + (sq2.x + sq2.y);
                h = fmaf(0.9f, h, 0.1f);
                h = fmaf(-0.2f, rl, h);

                yo[(size_t)t * DO] = q + bo;
            }

            if (l == 0) {
                __threadfence_block();
                *(volatile unsigned*)&bdone[rs] = (unsigned)tend;
            }
        }

        if (hfin) hfin[b * NH + l] = h;
    }
}

// ---------------------------------------------------------------------------
extern "C" void kernel_launch(void* const* d_in, const int* in_sizes, int n_in,
                              void* d_out, int out_size) {
    const float* inputs = (const float*)d_in[0];
    const float* W_in   = (const float*)d_in[1];
    const float* m_     = (const float*)d_in[2];
    const float* n_     = (const float*)d_in[3];
    const float* M_     = (const float*)d_in[4];
    const float* Nm_    = (const float*)d_in[5];
    const float* bias   = (const float*)d_in[6];
    const float* Wout   = (const float*)d_in[7];
    const float* bout   = (const float*)d_in[8];

    float* out = (float*)d_out;
    float* hf = nullptr;
    const long long need = (long long)BB * TT * NH + (long long)BB * NH;
    if ((long long)out_size >= need)
        hf = out + (size_t)BB * TT * NH;

    xproj_kernel<<<BB * TT / 64, 256>>>(inputs, W_in, bias);
    rnn_kernel<<<BB / 2, 96>>>(m_, n_, M_, Nm_, Wout, bout, out, hf);
}

// round 11
// speedup vs baseline: 1.2062x; 1.2062x over previous
#include <cuda_runtime.h>
#include <cstdint>

#define NH 32     // hidden
#define RK 6      // rank
#define BB 256    // batch
#define TT 2048   // time
#define DI 64     // input dim
#define DO 32     // output dim

#define RING   128
#define RINGM  127
#define XRING  128
#define XRINGM 127

#define L2E2 2.885390081777926815f   // 2*log2(e)

// Packed fp32x2 ops (Blackwell)
__device__ __forceinline__ float2 fma2(const float2 a, const float2 b, const float2 c) {
    float2 d;
    asm("fma.rn.f32x2 %0, %1, %2, %3;"
        : "=l"(*(unsigned long long*)&d)
        : "l"(*(const unsigned long long*)&a),
          "l"(*(const unsigned long long*)&b),
          "l"(*(const unsigned long long*)&c));
    return d;
}
__device__ __forceinline__ float2 add2(const float2 a, const float2 b) {
    float2 d;
    asm("add.rn.f32x2 %0, %1, %2;"
        : "=l"(*(unsigned long long*)&d)
        : "l"(*(const unsigned long long*)&a),
          "l"(*(const unsigned long long*)&b));
    return d;
}

// ---------------------------------------------------------------------------
// Single fused kernel. One block (96 thr) per batch chain.
//   Warp A (wid 0): critical p-recurrence (exact R6 code), r -> ring,
//                   x read from xring (gated on xprog).
//   Warp B (wid 1): trailing q/h/y from ring (exact R6 code).
//   Warp P (wid 2): produces x[t,n] = L2E2*(W_in[n,:]·u[t,:] + bias[n])
//                   into xring, staying <=96 steps ahead of A's progress.
// wid%4 -> SMSP: A, B, P each own a sub-partition; the latency-bound A chain
// never arbitrates against producer issue traffic (the R4 failure mode).
// tanh = 1 - 2r, r = 1/(exp2(pre')+1), pre' in 2log2e-scaled space.
// ---------------------------------------------------------------------------
__global__ void __launch_bounds__(96) rnn_kernel(
    const float* __restrict__ inp, const float* __restrict__ Win,
    const float* __restrict__ bias,
    const float* __restrict__ m, const float* __restrict__ nv,
    const float* __restrict__ Mm, const float* __restrict__ Nm,
    const float* __restrict__ Wout, const float* __restrict__ bout,
    float* __restrict__ out, float* __restrict__ hfin)
{
    __shared__ __align__(16) float ring[RING][NH];     // 16 KB: r values
    __shared__ __align__(16) float xring[XRING][NH];   // 16 KB: x-projection
    __shared__ __align__(16) float4 ustage[2][8 * DI / 4];  // 4 KB: u tiles
    __shared__ unsigned progress;   // steps published by A (every 32)
    __shared__ unsigned bdone;      // steps consumed by B
    __shared__ unsigned xprog;      // steps produced by P (every 8)

    const int b   = blockIdx.x;
    const int wid = threadIdx.x >> 5;
    const int l   = threadIdx.x & 31;

    if (threadIdx.x == 0) { progress = 0u; bdone = 0u; xprog = 0u; }
    __syncthreads();

    if (wid == 0) {
        // ================= WARP A: critical chain (R6) =================
        float Ml[RK];
        const float ml = m[l];
        #pragma unroll
        for (int j = 0; j < RK; j++) Ml[j] = Mm[l * RK + j];

        float2 wr2[NH / 2];
        float wrsum = 0.f;
        #pragma unroll
        for (int k = 0; k < NH; k += 2) {
            float s0 = ml * nv[k], s1 = ml * nv[k + 1];
            #pragma unroll
            for (int j = 0; j < RK; j++) {
                s0 = fmaf(Ml[j], Nm[k * RK + j], s0);
                s1 = fmaf(Ml[j], Nm[(k + 1) * RK + j], s1);
            }
            wrsum += s0 + s1;
            wr2[k / 2] = make_float2(-0.2f * L2E2 * s0, -0.2f * L2E2 * s1);
        }
        wrsum *= 0.1f * L2E2;

        float p = 0.f;

        // initial gate + prefetch of steps 0..7 from xring
        while (*(volatile unsigned*)&xprog < 8u) __nanosleep(100);
        float xa[8], xn[8];
        #pragma unroll
        for (int i = 0; i < 8; i++) xa[i] = xring[i][l];

        for (int c = 0; c < TT / 8; c++) {
            const int t0 = c * 8;
            if (c + 1 < TT / 8) {
                // gate: x for t0+8..t0+15 must be produced
                while (*(volatile unsigned*)&xprog < (unsigned)(t0 + 16))
                    __nanosleep(64);
                #pragma unroll
                for (int i = 0; i < 8; i++) xn[i] = xring[(t0 + 8 + i) & XRINGM][l];
            }
            #pragma unroll
            for (int s = 0; s < 8; s++) {
                const int t = t0 + s;
                const float pre = p + xa[s];
                float e;
                asm("ex2.approx.f32 %0, %1;" : "=f"(e) : "f"(pre));
                float r;
                asm("rcp.approx.f32 %0, %1;" : "=f"(r) : "f"(e + 1.0f));

                const float pbase = fmaf(0.9f, p, wrsum);   // in MUFU shadow

                ring[t & RINGM][l] = r;
                __syncwarp();

                const float4* r4p = (const float4*)ring[t & RINGM];
                float2 ap0 = make_float2(0.f, 0.f), ap1 = ap0, ap2 = ap0, ap3 = ap0;
                #pragma unroll
                for (int j = 0; j < NH / 4; j++) {
                    const float4 r4 = r4p[j];
                    const float2 lo = make_float2(r4.x, r4.y);
                    const float2 hi = make_float2(r4.z, r4.w);
                    float2 acc = (j & 3) == 0 ? ap0 : (j & 3) == 1 ? ap1 : (j & 3) == 2 ? ap2 : ap3;
                    acc = fma2(wr2[2 * j + 0], lo, acc);
                    acc = fma2(wr2[2 * j + 1], hi, acc);
                    if ((j & 3) == 0) ap0 = acc; else if ((j & 3) == 1) ap1 = acc;
                    else if ((j & 3) == 2) ap2 = acc; else ap3 = acc;
                }
                const float2 sp2 = add2(add2(ap0, ap1), add2(ap2, ap3));
                p = pbase + (sp2.x + sp2.y);
            }
            #pragma unroll
            for (int i = 0; i < 8; i++) xa[i] = xn[i];

            if ((c & 3) == 3) {
                __threadfence_block();
                __syncwarp();
                if (l == 0)
                    *(volatile unsigned*)&progress = (unsigned)(t0 + 8);
                if (l == 0) {
                    while ((int)(t0 + 8) - (int)(*(volatile unsigned*)&bdone) > RING - 64)
                        __nanosleep(100);
                }
                __syncwarp();
            }
        }
    } else if (wid == 1) {
        // ================= WARP B: trailing q/h/y (R6) =================
        float2 wo2[NH / 2];
        float wosum = 0.f;
        #pragma unroll
        for (int k = 0; k < NH; k += 2) {
            const float o0 = Wout[l * NH + k], o1 = Wout[l * NH + k + 1];
            wosum += o0 + o1;
            wo2[k / 2] = make_float2(-0.2f * o0, -0.2f * o1);
        }
        wosum *= 0.1f;
        const float bo = bout[l];

        float* yo = out + (size_t)b * TT * DO + l;
        float q = 0.f, h = 0.f;

        for (int blk = 0; blk < TT / 32; blk++) {
            const int tend = (blk + 1) * 32;
            if (l == 0) {
                while ((int)(*(volatile unsigned*)&progress) < tend)
                    __nanosleep(150);
            }
            __syncwarp();
            __threadfence_block();   // acquire: ring writes visible

            for (int t = blk * 32; t < tend; t++) {
                const float4* r4p = (const float4*)ring[t & RINGM];
                float2 aq0 = make_float2(0.f, 0.f), aq1 = aq0, aq2 = aq0, aq3 = aq0;
                #pragma unroll
                for (int j = 0; j < NH / 4; j++) {
                    const float4 r4 = r4p[j];
                    const float2 lo = make_float2(r4.x, r4.y);
                    const float2 hi = make_float2(r4.z, r4.w);
                    float2 acc = (j & 3) == 0 ? aq0 : (j & 3) == 1 ? aq1 : (j & 3) == 2 ? aq2 : aq3;
                    acc = fma2(wo2[2 * j + 0], lo, acc);
                    acc = fma2(wo2[2 * j + 1], hi, acc);
                    if ((j & 3) == 0) aq0 = acc; else if ((j & 3) == 1) aq1 = acc;
                    else if ((j & 3) == 2) aq2 = acc; else aq3 = acc;
                }
                const float2 sq2 = add2(add2(aq0, aq1), add2(aq2, aq3));
                const float rl = ring[t & RINGM][l];

                q = fmaf(0.9f, q, wosum) + (sq2.x + sq2.y);
                h = fmaf(0.9f, h, 0.1f);
                h = fmaf(-0.2f, rl, h);

                yo[(size_t)t * DO] = q + bo;
            }

            if (l == 0) {
                __threadfence_block();
                *(volatile unsigned*)&bdone = (unsigned)tend;
            }
        }

        if (hfin) hfin[b * NH + l] = h;
    } else {
        // ================= WARP P: x-projection producer =================
        // lane n holds W_in row n in registers; u tiles staged via smem.
        float2 w2[DI / 2];
        #pragma unroll
        for (int i = 0; i < DI; i += 2)
            w2[i / 2] = make_float2(Win[l * DI + i], Win[l * DI + i + 1]);
        const float bn = bias[l];

        const float* ub = inp + (size_t)b * TT * DI;

        // stage tile 0 (8 t-steps, 2 KB, coalesced)
        {
            const float4* g = (const float4*)ub;
            #pragma unroll
            for (int k = 0; k < 4; k++) ustage[0][l + 32 * k] = g[l + 32 * k];
        }
        __syncwarp();

        for (int tile = 0; tile < TT / 8; tile++) {
            const int t0 = tile * 8;
            const int buf = tile & 1;

            // gate: don't run >96 steps ahead of A (xring overwrite safety)
            while ((int)t0 - (int)(*(volatile unsigned*)&progress) > 96)
                __nanosleep(200);

            // prefetch next u tile into registers (LDG latency hidden by compute)
            float4 nx[4];
            if (tile + 1 < TT / 8) {
                const float4* g = (const float4*)(ub + (size_t)(t0 + 8) * DI);
                #pragma unroll
                for (int k = 0; k < 4; k++) nx[k] = g[l + 32 * k];
            }

            #pragma unroll
            for (int s = 0; s < 8; s++) {
                const float4* u4p = &ustage[buf][s * 16];
                float2 a0 = make_float2(0.f, 0.f), a1 = a0, a2 = a0, a3 = a0;
                #pragma unroll
                for (int i4 = 0; i4 < 16; i4++) {
                    const float4 u4 = u4p[i4];   // broadcast LDS.128
                    float2 acc = (i4 & 3) == 0 ? a0 : (i4 & 3) == 1 ? a1 : (i4 & 3) == 2 ? a2 : a3;
                    acc = fma2(w2[2 * i4 + 0], make_float2(u4.x, u4.y), acc);
                    acc = fma2(w2[2 * i4 + 1], make_float2(u4.z, u4.w), acc);
                    if ((i4 & 3) == 0) a0 = acc; else if ((i4 & 3) == 1) a1 = acc;
                    else if ((i4 & 3) == 2) a2 = acc; else a3 = acc;
                }
                const float2 sv = add2(add2(a0, a1), add2(a2, a3));
                xring[(t0 + s) & XRINGM][l] = L2E2 * (sv.x + sv.y + bn);
            }

            // commit staged next tile, then publish coverage
            if (tile + 1 < TT / 8) {
                #pragma unroll
                for (int k = 0; k < 4; k++) ustage[buf ^ 1][l + 32 * k] = nx[k];
            }
            __threadfence_block();
            __syncwarp();
            if (l == 0)
                *(volatile unsigned*)&xprog = (unsigned)(t0 + 8);
        }
    }
}

// ---------------------------------------------------------------------------
extern "C" void kernel_launch(void* const* d_in, const int* in_sizes, int n_in,
                              void* d_out, int out_size) {
    const float* inputs = (const float*)d_in[0];
    const float* W_in   = (const float*)d_in[1];
    const float* m_     = (const float*)d_in[2];
    const float* n_     = (const float*)d_in[3];
    const float* M_     = (const float*)d_in[4];
    const float* Nm_    = (const float*)d_in[5];
    const float* bias   = (const float*)d_in[6];
    const float* Wout   = (const float*)d_in[7];
    const float* bout   = (const float*)d_in[8];

    float* out = (float*)d_out;
    float* hf = nullptr;
    const long long need = (long long)BB * TT * NH + (long long)BB * NH;
    if ((long long)out_size >= need)
        hf = out + (size_t)BB * TT * NH;

    rnn_kernel<<<BB, 96>>>(inputs, W_in, bias, m_, n_, M_, Nm_, Wout, bout, out, hf);
}

// round 12
// speedup vs baseline: 1.4079x; 1.1672x over previous
#include <cuda_runtime.h>
#include <cstdint>

#define NH 32     // hidden
#define RK 6      // rank
#define BB 256    // batch
#define TT 2048   // time
#define DI 64     // input dim
#define DO 32     // output dim

#define RING  128
#define RINGM 127

// 64 MB scratch for pre-scaled x-projection (device global: allocation-free)
__device__ float g_xp[(size_t)BB * TT * NH];

#define L2E2 2.885390081777926815f   // 2*log2(e)

// Packed fp32x2 ops (Blackwell)
__device__ __forceinline__ float2 fma2(const float2 a, const float2 b, const float2 c) {
    float2 d;
    asm("fma.rn.f32x2 %0, %1, %2, %3;"
        : "=l"(*(unsigned long long*)&d)
        : "l"(*(const unsigned long long*)&a),
          "l"(*(const unsigned long long*)&b),
          "l"(*(const unsigned long long*)&c));
    return d;
}
__device__ __forceinline__ float2 add2(const float2 a, const float2 b) {
    float2 d;
    asm("add.rn.f32x2 %0, %1, %2;"
        : "=l"(*(unsigned long long*)&d)
        : "l"(*(const unsigned long long*)&a),
          "l"(*(const unsigned long long*)&b));
    return d;
}

// ---------------------------------------------------------------------------
// Kernel 1 (v2): g_xp[b,t,n] = L2E2*(sum_i inputs[b,t,i]*W_in[n,i] + bias[n])
// Register-tiled: each lane computes a 4-row x 4-output tile, so every
// float4 LDS (u or W) feeds 8 fma2 (vs 2 before) — halves LDS-instr count,
// which ncu showed to be the binding LSU resource.
// Block: 128 threads (4 warps), 64 rows. Warp w -> rows [w*16,(w+1)*16).
// Lane: ng = l>>2 (output quad n in [4ng,4ng+4)), rg = l&3;
//       rows handled = w*16 + rg + 4*ri, ri in 0..3.
// u smem: [64][68] floats (pad 68 => rg-lanes hit distinct bank quads).
// W smem: chunk-major float4 with swizzle (n&3)*8 + (n>>2) => per-nj LDS
//         conflict-free across ng-lanes.
// ---------------------------------------------------------------------------
__global__ void __launch_bounds__(128) xproj_kernel(
    const float* __restrict__ inp, const float* __restrict__ Win,
    const float* __restrict__ bias)
{
    __shared__ __align__(16) float usm[64 * 68];        // 17.0 KB (pad 68)
    __shared__ __align__(16) float4 wsm4[16 * 32];      // 8 KB, swizzled

    const int tid = threadIdx.x;

    // Stage W: idx over 512 float4; n = idx>>4, c = idx&15
    const float4* wg = (const float4*)Win;
    #pragma unroll
    for (int it = 0; it < 4; it++) {
        const int idx = tid + 128 * it;
        const int n = idx >> 4, c = idx & 15;
        wsm4[c * 32 + (n & 3) * 8 + (n >> 2)] = wg[idx];
    }

    // Stage u: 64 rows x 16 float4, padded row stride 17 float4
    const size_t base = (size_t)blockIdx.x * 64 * DI;
    const float4* ug = (const float4*)(inp + base);
    float4* us4 = (float4*)usm;
    #pragma unroll
    for (int it = 0; it < 8; it++) {
        const int idx = tid + 128 * it;
        const int row = idx >> 4, c4 = idx & 15;
        us4[row * 17 + c4] = ug[idx];
    }
    __syncthreads();

    const int w  = tid >> 5;
    const int l  = tid & 31;
    const int ng = l >> 2;
    const int rg = l & 3;
    const int rbase = w * 16;

    const float4* usr = us4 + (rbase + rg) * 17;   // +4*ri*17 per ri

    float2 acc[4][4];
    #pragma unroll
    for (int ri = 0; ri < 4; ri++)
        #pragma unroll
        for (int nj = 0; nj < 4; nj++) acc[ri][nj] = make_float2(0.f, 0.f);

    #pragma unroll
    for (int c = 0; c < 16; c++) {
        float4 u4[4], w4[4];
        #pragma unroll
        for (int ri = 0; ri < 4; ri++) u4[ri] = usr[ri * 4 * 17 + c];
        #pragma unroll
        for (int nj = 0; nj < 4; nj++) w4[nj] = wsm4[c * 32 + nj * 8 + ng];
        #pragma unroll
        for (int ri = 0; ri < 4; ri++) {
            const float2 ulo = make_float2(u4[ri].x, u4[ri].y);
            const float2 uhi = make_float2(u4[ri].z, u4[ri].w);
            #pragma unroll
            for (int nj = 0; nj < 4; nj++) {
                acc[ri][nj] = fma2(ulo, make_float2(w4[nj].x, w4[nj].y), acc[ri][nj]);
                acc[ri][nj] = fma2(uhi, make_float2(w4[nj].z, w4[nj].w), acc[ri][nj]);
            }
        }
    }

    const float4 b4 = *(const float4*)(bias + ng * 4);
    const size_t row0 = (size_t)blockIdx.x * 64 + rbase + rg;
    #pragma unroll
    for (int ri = 0; ri < 4; ri++) {
        float4 o;
        o.x = L2E2 * (acc[ri][0].x + acc[ri][0].y + b4.x);
        o.y = L2E2 * (acc[ri][1].x + acc[ri][1].y + b4.y);
        o.z = L2E2 * (acc[ri][2].x + acc[ri][2].y + b4.z);
        o.w = L2E2 * (acc[ri][3].x + acc[ri][3].y + b4.w);
        *(float4*)&g_xp[(row0 + ri * 4) * NH + ng * 4] = o;
    }
}

// ---------------------------------------------------------------------------
// Kernel 2: warp-specialized recurrence — EXACT R6 (proven 226us).
//   Warp A (wid 0): critical p-recurrence, writes r_t to a smem ring.
//   Warp B (wid 1): trails A, computes q/h/y from the ring.
// tanh = 1 - 2r, r = 1/(exp2(pre')+1), pre' in 2log2e-scaled space.
// ---------------------------------------------------------------------------
__global__ void __launch_bounds__(64) rnn_kernel(
    const float* __restrict__ m, const float* __restrict__ nv,
    const float* __restrict__ Mm, const float* __restrict__ Nm,
    const float* __restrict__ Wout, const float* __restrict__ bout,
    float* __restrict__ out, float* __restrict__ hfin)
{
    __shared__ __align__(16) float ring[RING][NH];
    __shared__ unsigned progress;
    __shared__ unsigned bdone;

    const int b   = blockIdx.x;
    const int wid = threadIdx.x >> 5;
    const int l   = threadIdx.x & 31;

    if (threadIdx.x == 0) { progress = 0u; bdone = 0u; }
    __syncthreads();

    if (wid == 0) {
        // ================= WARP A: critical chain =================
        float Ml[RK];
        const float ml = m[l];
        #pragma unroll
        for (int j = 0; j < RK; j++) Ml[j] = Mm[l * RK + j];

        float2 wr2[NH / 2];
        float wrsum = 0.f;
        #pragma unroll
        for (int k = 0; k < NH; k += 2) {
            float s0 = ml * nv[k], s1 = ml * nv[k + 1];
            #pragma unroll
            for (int j = 0; j < RK; j++) {
                s0 = fmaf(Ml[j], Nm[k * RK + j], s0);
                s1 = fmaf(Ml[j], Nm[(k + 1) * RK + j], s1);
            }
            wrsum += s0 + s1;
            wr2[k / 2] = make_float2(-0.2f * L2E2 * s0, -0.2f * L2E2 * s1);
        }
        wrsum *= 0.1f * L2E2;

        const float* xp = g_xp + (size_t)b * TT * NH + l;
        float p = 0.f;

        float xa[8], xn[8];
        #pragma unroll
        for (int i = 0; i < 8; i++) xa[i] = xp[(size_t)i * NH];

        for (int c = 0; c < TT / 8; c++) {
            const int t0 = c * 8;
            if (c + 1 < TT / 8) {
                #pragma unroll
                for (int i = 0; i < 8; i++) xn[i] = xp[(size_t)(t0 + 8 + i) * NH];
            }
            #pragma unroll
            for (int s = 0; s < 8; s++) {
                const int t = t0 + s;
                const float pre = p + xa[s];
                float e;
                asm("ex2.approx.f32 %0, %1;" : "=f"(e) : "f"(pre));
                float r;
                asm("rcp.approx.f32 %0, %1;" : "=f"(r) : "f"(e + 1.0f));

                const float pbase = fmaf(0.9f, p, wrsum);   // in MUFU shadow

                ring[t & RINGM][l] = r;
                __syncwarp();

                const float4* r4p = (const float4*)ring[t & RINGM];
                float2 ap0 = make_float2(0.f, 0.f), ap1 = ap0, ap2 = ap0, ap3 = ap0;
                #pragma unroll
                for (int j = 0; j < NH / 4; j++) {
                    const float4 r4 = r4p[j];
                    const float2 lo = make_float2(r4.x, r4.y);
                    const float2 hi = make_float2(r4.z, r4.w);
                    float2 acc = (j & 3) == 0 ? ap0 : (j & 3) == 1 ? ap1 : (j & 3) == 2 ? ap2 : ap3;
                    acc = fma2(wr2[2 * j + 0], lo, acc);
                    acc = fma2(wr2[2 * j + 1], hi, acc);
                    if ((j & 3) == 0) ap0 = acc; else if ((j & 3) == 1) ap1 = acc;
                    else if ((j & 3) == 2) ap2 = acc; else ap3 = acc;
                }
                const float2 sp2 = add2(add2(ap0, ap1), add2(ap2, ap3));
                p = pbase + (sp2.x + sp2.y);
            }
            #pragma unroll
            for (int i = 0; i < 8; i++) xa[i] = xn[i];

            if ((c & 3) == 3) {
                __threadfence_block();
                __syncwarp();
                if (l == 0)
                    *(volatile unsigned*)&progress = (unsigned)(t0 + 8);
                if (l == 0) {
                    while ((int)(t0 + 8) - (int)(*(volatile unsigned*)&bdone) > RING - 64)
                        __nanosleep(100);
                }
                __syncwarp();
            }
        }
    } else {
        // ================= WARP B: trailing q/h/y =================
        float2 wo2[NH / 2];
        float wosum = 0.f;
        #pragma unroll
        for (int k = 0; k < NH; k += 2) {
            const float o0 = Wout[l * NH + k], o1 = Wout[l * NH + k + 1];
            wosum += o0 + o1;
            wo2[k / 2] = make_float2(-0.2f * o0, -0.2f * o1);
        }
        wosum *= 0.1f;
        const float bo = bout[l];

        float* yo = out + (size_t)b * TT * DO + l;
        float q = 0.f, h = 0.f;

        for (int blk = 0; blk < TT / 32; blk++) {
            const int tend = (blk + 1) * 32;
            if (l == 0) {
                while ((int)(*(volatile unsigned*)&progress) < tend)
                    __nanosleep(150);
            }
            __syncwarp();
            __threadfence_block();

            for (int t = blk * 32; t < tend; t++) {
                const float4* r4p = (const float4*)ring[t & RINGM];
                float2 aq0 = make_float2(0.f, 0.f), aq1 = aq0, aq2 = aq0, aq3 = aq0;
                #pragma unroll
                for (int j = 0; j < NH / 4; j++) {
                    const float4 r4 = r4p[j];
                    const float2 lo = make_float2(r4.x, r4.y);
                    const float2 hi = make_float2(r4.z, r4.w);
                    float2 acc = (j & 3) == 0 ? aq0 : (j & 3) == 1 ? aq1 : (j & 3) == 2 ? aq2 : aq3;
                    acc = fma2(wo2[2 * j + 0], lo, acc);
                    acc = fma2(wo2[2 * j + 1], hi, acc);
                    if ((j & 3) == 0) aq0 = acc; else if ((j & 3) == 1) aq1 = acc;
                    else if ((j & 3) == 2) aq2 = acc; else aq3 = acc;
                }
                const float2 sq2 = add2(add2(aq0, aq1), add2(aq2, aq3));
                const float rl = ring[t & RINGM][l];

                q = fmaf(0.9f, q, wosum) + (sq2.x + sq2.y);
                h = fmaf(0.9f, h, 0.1f);
                h = fmaf(-0.2f, rl, h);

                yo[(size_t)t * DO] = q + bo;
            }

            if (l == 0) {
                __threadfence_block();
                *(volatile unsigned*)&bdone = (unsigned)tend;
            }
        }

        if (hfin) hfin[b * NH + l] = h;
    }
}

// ---------------------------------------------------------------------------
extern "C" void kernel_launch(void* const* d_in, const int* in_sizes, int n_in,
                              void* d_out, int out_size) {
    const float* inputs = (const float*)d_in[0];
    const float* W_in   = (const float*)d_in[1];
    const float* m_     = (const float*)d_in[2];
    const float* n_     = (const float*)d_in[3];
    const float* M_     = (const float*)d_in[4];
    const float* Nm_    = (const float*)d_in[5];
    const float* bias   = (const float*)d_in[6];
    const float* Wout   = (const float*)d_in[7];
    const float* bout   = (const float*)d_in[8];

    float* out = (float*)d_out;
    float* hf = nullptr;
    const long long need = (long long)BB * TT * NH + (long long)BB * NH;
    if ((long long)out_size >= need)
        hf = out + (size_t)BB * TT * NH;

    xproj_kernel<<<BB * TT / 64, 128>>>(inputs, W_in, bias);
    rnn_kernel<<<BB, 64>>>(m_, n_, M_, Nm_, Wout, bout, out, hf);
}